// round 2
// baseline (speedup 1.0000x reference)
#include <cuda_runtime.h>

#define BATCH   2
#define CF      64
#define NXD     468
#define NYD     468
#define GRID    (NXD * NYD)      // 219024
#define NP_PER  60000
#define HRD     48
#define WRD     512
#define PLANE4  (GRID / 4)       // 54756

// Winner-index maps: [0 .. B*G) spatial, [B*G .. 2*B*G) bev. -1 = empty.
__device__ __align__(16) int g_win[2 * BATCH * GRID];

__global__ void k_init(int n) {
    int i = blockIdx.x * blockDim.x + threadIdx.x;
    if (i < n) g_win[i] = -1;
}

// Spatial scatter: lin = coords[:,1] + coords[:,2]*NX + coords[:,3]
// last-write-wins == highest point index wins (serial XLA scatter order).
__global__ void k_scat_spat(const int* __restrict__ vc, int npts) {
    int p = blockIdx.x * blockDim.x + threadIdx.x;
    if (p >= npts) return;
    int b   = vc[p * 4 + 0];
    int lin = vc[p * 4 + 1] + vc[p * 4 + 2] * NXD + vc[p * 4 + 3];
    if (b < 0 || b >= BATCH || lin < 0 || lin >= GRID) return;  // mode=drop safety
    atomicMax(&g_win[b * GRID + lin], p);
}

// BEV scatter: validity + pixel quantization exactly per reference.
// XLA (fast-math arcp) rewrites  v / 0.16f  ->  v * (1/0.16f), and the
// float32-rounded reciprocal is EXACTLY 6.25f. Match it with an exact
// round-to-nearest multiply so boundary pixels quantize identically.
__global__ void k_scat_bev(const float* __restrict__ lp, int npts) {
    int p = blockIdx.x * blockDim.x + threadIdx.x;
    if (p >= npts) return;
    float x = lp[p * 5 + 1];
    float y = lp[p * 5 + 2];
    bool valid = (x > 0.0f) && (x < 69.12f) && (y > -39.68f) && (y < 39.68f)
              && (x >= 0.0f) && (x < 468.0f) && (y >= 0.0f) && (y < 468.0f);
    if (!valid) return;
    // astype(int32) truncates toward zero.
    int xi = (int)__fmul_rn(-y, 6.25f) + 248;   // XOFF
    int yi = (int)__fmul_rn(-x, 6.25f) + 432;   // YOFF
    xi = min(max(xi, 0), 495);                  // clip to XIMG_MAX
    yi = min(max(yi, 0), 431);                  // clip to YIMG_MAX
    if (xi >= NXD) return;                      // mode='drop'
    int b = p / NP_PER;
    // bev plane index: out[b, 64+c, y_img, x_img]  ->  cell = yi*468 + xi
    atomicMax(&g_win[BATCH * GRID + b * GRID + yi * NXD + xi], p);
}

// Gather: one thread = 4 consecutive output pixels of one (b, ch) plane.
// Coalesced float4 stores; random reads hit L2 (inputs fit in 126 MB L2).
__global__ void k_gather(const float* __restrict__ pf,
                         const float* __restrict__ ro,
                         const int*   __restrict__ lx,
                         const int*   __restrict__ ly,
                         const float* __restrict__ lp,
                         float*       __restrict__ out) {
    int plane = blockIdx.y;           // 0..255  = b*128 + ch
    int b  = plane >> 7;
    int ch = plane & 127;
    int i4 = blockIdx.x * blockDim.x + threadIdx.x;
    if (i4 >= PLANE4) return;

    float vv[4];
    if (ch < CF) {
        int4 w4 = *(const int4*)&g_win[b * GRID + i4 * 4];
        const int w[4] = {w4.x, w4.y, w4.z, w4.w};
        #pragma unroll
        for (int k = 0; k < 4; k++) {
            int wi = w[k];
            vv[k] = (wi >= 0) ? pf[wi * CF + ch] : 0.0f;
        }
    } else {
        int c = ch - CF;
        int4 w4 = *(const int4*)&g_win[BATCH * GRID + b * GRID + i4 * 4];
        const int w[4] = {w4.x, w4.y, w4.z, w4.w};
        #pragma unroll
        for (int k = 0; k < 4; k++) {
            int wi = w[k];
            float val = 0.0f;
            if (wi >= 0) {
                float z = lp[wi * 5 + 3];
                z = fminf(fmaxf(z, -2.0f), 4.0f);
                int xx = lx[wi * 2 + 1];
                int yy = ly[wi * 2 + 1];
                val = __fmul_rn(z, ro[((b * CF + c) * HRD + yy) * WRD + xx]);
            }
            vv[k] = val;
        }
    }
    float4 v = make_float4(vv[0], vv[1], vv[2], vv[3]);
    *(float4*)&out[(size_t)plane * GRID + (size_t)i4 * 4] = v;
}

extern "C" void kernel_launch(void* const* d_in, const int* in_sizes, int n_in,
                              void* d_out, int out_size) {
    const float* pf = (const float*)d_in[0];   // pillar_features (B*P_PER, 64)
    const int*   vc = (const int*)  d_in[1];   // voxel_coords    (B*P_PER, 4)
    const float* ro = (const float*)d_in[2];   // range_out       (B, 64, 48, 512)
    const int*   lx = (const int*)  d_in[3];   // laser_x         (B*NP, 2)
    const int*   ly = (const int*)  d_in[4];   // laser_y         (B*NP, 2)
    const float* lp = (const float*)d_in[5];   // laser_points    (B*NP, 5)
    float* out = (float*)d_out;

    int n_pillar = in_sizes[1] / 4;
    int n_laser  = in_sizes[5] / 5;

    int n_win = 2 * BATCH * GRID;
    k_init<<<(n_win + 511) / 512, 512>>>(n_win);
    k_scat_spat<<<(n_pillar + 255) / 256, 256>>>(vc, n_pillar);
    k_scat_bev<<<(n_laser + 255) / 256, 256>>>(lp, n_laser);

    dim3 gg((PLANE4 + 255) / 256, 2 * CF * BATCH);  // (214, 256)
    k_gather<<<gg, 256>>>(pf, ro, lx, ly, lp, out);
}

// round 3
// speedup vs baseline: 1.2093x; 1.2093x over previous
#include <cuda_runtime.h>

#define BATCH   2
#define CF      64
#define NXD     468
#define NYD     468
#define GRID    (NXD * NYD)      // 219024
#define NP_PER  60000
#define HRD     48
#define WRD     512
#define RSP     (HRD * WRD)      // 24576 range-image pixels per (b,ch)
#define TCELL   16               // cells per gather tile (GRID % 16 == 0)
#define NTILES  (GRID / TCELL)   // 13689
#define SROW    132              // smem row stride (floats): 132*4=528, 16B aligned

// Winner-index maps: [0 .. B*G) spatial, [B*G .. 2*B*G) bev. -1 = empty.
__device__ __align__(16) int g_win[2 * BATCH * GRID];
// Channel-last transposed range_out: [B][RSP][64]
__device__ __align__(16) float g_rot[BATCH * RSP * CF];

__global__ void k_init(int n) {
    int i = blockIdx.x * blockDim.x + threadIdx.x;
    if (i < n) g_win[i] = -1;
}

// Spatial scatter: last-write-wins == highest point index wins.
__global__ void k_scat_spat(const int* __restrict__ vc, int npts) {
    int p = blockIdx.x * blockDim.x + threadIdx.x;
    if (p >= npts) return;
    int b   = vc[p * 4 + 0];
    int lin = vc[p * 4 + 1] + vc[p * 4 + 2] * NXD + vc[p * 4 + 3];
    if (b < 0 || b >= BATCH || lin < 0 || lin >= GRID) return;
    atomicMax(&g_win[b * GRID + lin], p);
}

// BEV scatter. XLA's arcp rewrite makes v/0.16f == v*6.25f exactly (verified
// rel_err == 0.0); keep __fmul_rn so fast-math can't touch it.
__global__ void k_scat_bev(const float* __restrict__ lp, int npts) {
    int p = blockIdx.x * blockDim.x + threadIdx.x;
    if (p >= npts) return;
    float x = lp[p * 5 + 1];
    float y = lp[p * 5 + 2];
    bool valid = (x > 0.0f) && (x < 69.12f) && (y > -39.68f) && (y < 39.68f)
              && (x >= 0.0f) && (x < 468.0f) && (y >= 0.0f) && (y < 468.0f);
    if (!valid) return;
    int xi = (int)__fmul_rn(-y, 6.25f) + 248;   // XOFF
    int yi = (int)__fmul_rn(-x, 6.25f) + 432;   // YOFF
    xi = min(max(xi, 0), 495);
    yi = min(max(yi, 0), 431);
    if (xi >= NXD) return;                      // mode='drop'
    int b = p / NP_PER;
    atomicMax(&g_win[BATCH * GRID + b * GRID + yi * NXD + xi], p);
}

// Transpose range_out (B,64,48*512) -> g_rot (B,48*512,64), 32x32 smem tiles.
__global__ void k_rot_transpose(const float* __restrict__ ro) {
    __shared__ float tile[32][33];
    int b  = blockIdx.z;
    int s0 = blockIdx.x * 32;               // pixel index base
    int c0 = blockIdx.y * 32;               // channel base
    int tx = threadIdx.x, ty = threadIdx.y; // (32, 8)
    #pragma unroll
    for (int j = 0; j < 4; j++) {
        int c = c0 + ty + j * 8;
        tile[ty + j * 8][tx] = ro[((size_t)(b * CF + c)) * RSP + s0 + tx];
    }
    __syncthreads();
    #pragma unroll
    for (int j = 0; j < 4; j++) {
        int s = s0 + ty + j * 8;
        g_rot[((size_t)(b * RSP + s)) * CF + c0 + tx] = tile[tx][ty + j * 8];
    }
}

// Tiled gather: one block = 16 cells x 128 channels (8 KB of output).
// Phase 0: resolve winners once per cell. Phase 1: float4 row-loads from
// pf / g_rot (full-line reads). Phase 2: smem transpose -> coalesced float4
// stores along cells.
__global__ void __launch_bounds__(256) k_gather(
        const float* __restrict__ pf,
        const int*   __restrict__ lx,
        const int*   __restrict__ ly,
        const float* __restrict__ lp,
        float*       __restrict__ out) {
    __shared__ float s_val[TCELL][SROW];    // [cell][ch] (ch 0..127 used)
    __shared__ float s_zc[TCELL];
    __shared__ int   s_off[TCELL];
    __shared__ int   s_wiS[TCELL];

    int tile = blockIdx.x;                  // 0..NTILES-1
    int b    = blockIdx.y;                  // 0..1
    int t    = threadIdx.x;

    if (t < TCELL) {
        int cell = tile * TCELL + t;
        s_wiS[t] = g_win[b * GRID + cell];
        int wiB  = g_win[BATCH * GRID + b * GRID + cell];
        float zc = 0.0f; int off = -1;
        if (wiB >= 0) {
            float z = lp[wiB * 5 + 3];
            zc  = fminf(fmaxf(z, -2.0f), 4.0f);
            off = b * RSP + ly[wiB * 2 + 1] * WRD + lx[wiB * 2 + 1];
        }
        s_zc[t] = zc; s_off[t] = off;
    }
    __syncthreads();

    {   // Phase 1: each of 256 threads loads one float4 from each half.
        int cell = t >> 4;                  // 0..15
        int v    = t & 15;                  // 0..15 -> channel 4v..4v+3
        int wi = s_wiS[cell];
        float4 a = make_float4(0.f, 0.f, 0.f, 0.f);
        if (wi >= 0) a = *(const float4*)&pf[(size_t)wi * CF + v * 4];
        *(float4*)&s_val[cell][v * 4] = a;

        int off = s_off[cell];
        float zc = s_zc[cell];
        float4 r = make_float4(0.f, 0.f, 0.f, 0.f);
        if (off >= 0) {
            r = *(const float4*)&g_rot[(size_t)off * CF + v * 4];
            r.x = __fmul_rn(zc, r.x); r.y = __fmul_rn(zc, r.y);
            r.z = __fmul_rn(zc, r.z); r.w = __fmul_rn(zc, r.w);
        }
        *(float4*)&s_val[cell][CF + v * 4] = r;
    }
    __syncthreads();

    // Phase 2: 512 float4 stores (128 ch x 4 cell-vectors), coalesced.
    size_t base = (size_t)b * 128 * GRID + (size_t)tile * TCELL;
    #pragma unroll
    for (int s = t; s < 512; s += 256) {
        int ch = s >> 2;
        int cv = s & 3;
        float4 o;
        o.x = s_val[cv * 4 + 0][ch];
        o.y = s_val[cv * 4 + 1][ch];
        o.z = s_val[cv * 4 + 2][ch];
        o.w = s_val[cv * 4 + 3][ch];
        *(float4*)&out[base + (size_t)ch * GRID + cv * 4] = o;
    }
}

extern "C" void kernel_launch(void* const* d_in, const int* in_sizes, int n_in,
                              void* d_out, int out_size) {
    const float* pf = (const float*)d_in[0];   // pillar_features (B*P_PER, 64)
    const int*   vc = (const int*)  d_in[1];   // voxel_coords    (B*P_PER, 4)
    const float* ro = (const float*)d_in[2];   // range_out       (B, 64, 48, 512)
    const int*   lx = (const int*)  d_in[3];   // laser_x         (B*NP, 2)
    const int*   ly = (const int*)  d_in[4];   // laser_y         (B*NP, 2)
    const float* lp = (const float*)d_in[5];   // laser_points    (B*NP, 5)
    float* out = (float*)d_out;

    int n_pillar = in_sizes[1] / 4;
    int n_laser  = in_sizes[5] / 5;

    int n_win = 2 * BATCH * GRID;
    k_init<<<(n_win + 511) / 512, 512>>>(n_win);
    k_scat_spat<<<(n_pillar + 255) / 256, 256>>>(vc, n_pillar);
    k_scat_bev<<<(n_laser + 255) / 256, 256>>>(lp, n_laser);

    dim3 tb(32, 8);
    dim3 tg(RSP / 32, CF / 32, BATCH);         // (768, 2, 2)
    k_rot_transpose<<<tg, tb>>>(ro);

    dim3 gg(NTILES, BATCH);                    // (13689, 2)
    k_gather<<<gg, 256>>>(pf, lx, ly, lp, out);
}

// round 4
// speedup vs baseline: 1.5294x; 1.2647x over previous
#include <cuda_runtime.h>

#define BATCH   2
#define CF      64
#define NXD     468
#define NYD     468
#define GRID    (NXD * NYD)      // 219024
#define NP_PER  60000
#define HRD     48
#define WRD     512
#define RSP     (HRD * WRD)      // 24576
#define TCELL   32               // cells per gather tile (last tile has 16)
#define NTILES  ((GRID + TCELL - 1) / TCELL)   // 6846
#define SROW    129              // 129 % 32 == 1 -> conflict-free smem

// Winner-index maps: [0 .. B*G) spatial, [B*G .. 2*B*G) bev. -1 = empty.
__device__ __align__(16) int g_win[2 * BATCH * GRID];
// Channel-last transposed range_out: [B][RSP][64]
__device__ __align__(16) float g_rot[BATCH * RSP * CF];

// Fused scatter: first n_pillar threads do the spatial scatter, rest do BEV.
// Last-write-wins == highest point index wins (serial XLA scatter order).
// XLA's arcp rewrite makes v/0.16f == v*6.25f exactly (verified rel_err==0.0).
__global__ void k_scatter(const int* __restrict__ vc,
                          const float* __restrict__ lp,
                          int n_pillar, int n_laser) {
    int i = blockIdx.x * blockDim.x + threadIdx.x;
    if (i < n_pillar) {
        int b   = vc[i * 4 + 0];
        int lin = vc[i * 4 + 1] + vc[i * 4 + 2] * NXD + vc[i * 4 + 3];
        if (b < 0 || b >= BATCH || lin < 0 || lin >= GRID) return;
        atomicMax(&g_win[b * GRID + lin], i);
    } else {
        int p = i - n_pillar;
        if (p >= n_laser) return;
        float x = lp[p * 5 + 1];
        float y = lp[p * 5 + 2];
        bool valid = (x > 0.0f) && (x < 69.12f) && (y > -39.68f) && (y < 39.68f)
                  && (x >= 0.0f) && (x < 468.0f) && (y >= 0.0f) && (y < 468.0f);
        if (!valid) return;
        int xi = (int)__fmul_rn(-y, 6.25f) + 248;   // XOFF
        int yi = (int)__fmul_rn(-x, 6.25f) + 432;   // YOFF
        xi = min(max(xi, 0), 495);
        yi = min(max(yi, 0), 431);
        if (xi >= NXD) return;                      // mode='drop'
        int b = p / NP_PER;
        atomicMax(&g_win[BATCH * GRID + b * GRID + yi * NXD + xi], p);
    }
}

// Transpose range_out (B,64,48*512) -> g_rot (B,48*512,64), 32x32 smem tiles.
__global__ void k_rot_transpose(const float* __restrict__ ro) {
    __shared__ float tile[32][33];
    int b  = blockIdx.z;
    int s0 = blockIdx.x * 32;
    int c0 = blockIdx.y * 32;
    int tx = threadIdx.x, ty = threadIdx.y; // (32, 8)
    #pragma unroll
    for (int j = 0; j < 4; j++) {
        int c = c0 + ty + j * 8;
        tile[ty + j * 8][tx] = ro[((size_t)(b * CF + c)) * RSP + s0 + tx];
    }
    __syncthreads();
    #pragma unroll
    for (int j = 0; j < 4; j++) {
        int s = s0 + ty + j * 8;
        g_rot[((size_t)(b * RSP + s)) * CF + c0 + tx] = tile[tx][ty + j * 8];
    }
}

// Tiled gather: one block = 32 cells x 128 channels (16 KB of output).
// Phase 0: resolve winners once per cell.
// Phase 1: float4 gathers from pf / g_rot, scalar STS (conflict-free, SROW=129).
// Phase 2: conflict-free smem reads -> full-128B-line float4 stores per channel.
__global__ void __launch_bounds__(256) k_gather(
        const float* __restrict__ pf,
        const int*   __restrict__ lx,
        const int*   __restrict__ ly,
        const float* __restrict__ lp,
        float*       __restrict__ out) {
    __shared__ float s_val[TCELL][SROW];   // [cell][ch 0..127]
    __shared__ float s_zc[TCELL];
    __shared__ int   s_off[TCELL];
    __shared__ int   s_wiS[TCELL];

    int tile = blockIdx.x;
    int b    = blockIdx.y;
    int t    = threadIdx.x;
    int cell0  = tile * TCELL;
    int ncells = min(TCELL, GRID - cell0);

    if (t < TCELL) {
        int wiS = -1, wiB = -1;
        if (t < ncells) {
            wiS = g_win[b * GRID + cell0 + t];
            wiB = g_win[BATCH * GRID + b * GRID + cell0 + t];
        }
        s_wiS[t] = wiS;
        float zc = 0.0f; int off = -1;
        if (wiB >= 0) {
            float z = lp[wiB * 5 + 3];
            zc  = fminf(fmaxf(z, -2.0f), 4.0f);
            off = b * RSP + ly[wiB * 2 + 1] * WRD + lx[wiB * 2 + 1];
        }
        s_zc[t] = zc; s_off[t] = off;
    }
    __syncthreads();

    // Phase 1: items (cell, v), cell = i&31, v = i>>5 in 0..15.
    #pragma unroll
    for (int it = 0; it < 2; it++) {
        int i = t + it * 256;
        int cell = i & 31;
        int v    = i >> 5;
        int wi = s_wiS[cell];
        float4 a = make_float4(0.f, 0.f, 0.f, 0.f);
        if (wi >= 0) a = *(const float4*)&pf[(size_t)wi * CF + v * 4];
        s_val[cell][v * 4 + 0] = a.x;
        s_val[cell][v * 4 + 1] = a.y;
        s_val[cell][v * 4 + 2] = a.z;
        s_val[cell][v * 4 + 3] = a.w;

        int off = s_off[cell];
        float4 r = make_float4(0.f, 0.f, 0.f, 0.f);
        if (off >= 0) {
            float zc = s_zc[cell];
            r = *(const float4*)&g_rot[(size_t)off * CF + v * 4];
            r.x = __fmul_rn(zc, r.x); r.y = __fmul_rn(zc, r.y);
            r.z = __fmul_rn(zc, r.z); r.w = __fmul_rn(zc, r.w);
        }
        s_val[cell][CF + v * 4 + 0] = r.x;
        s_val[cell][CF + v * 4 + 1] = r.y;
        s_val[cell][CF + v * 4 + 2] = r.z;
        s_val[cell][CF + v * 4 + 3] = r.w;
    }
    __syncthreads();

    // Phase 2: 1024 float4 stores (128 ch x 8 cell-vectors). Per warp: 4
    // channels x 8 vectors = one full 128B line per channel row.
    size_t base = (size_t)b * 128 * GRID + (size_t)cell0;
    #pragma unroll
    for (int it = 0; it < 4; it++) {
        int s  = t + it * 256;
        int ch = s >> 3;
        int cv = s & 7;
        if (cv * 4 < ncells) {
            float4 o;
            o.x = s_val[cv * 4 + 0][ch];
            o.y = s_val[cv * 4 + 1][ch];
            o.z = s_val[cv * 4 + 2][ch];
            o.w = s_val[cv * 4 + 3][ch];
            *(float4*)&out[base + (size_t)ch * GRID + cv * 4] = o;
        }
    }
}

extern "C" void kernel_launch(void* const* d_in, const int* in_sizes, int n_in,
                              void* d_out, int out_size) {
    const float* pf = (const float*)d_in[0];   // pillar_features (B*P_PER, 64)
    const int*   vc = (const int*)  d_in[1];   // voxel_coords    (B*P_PER, 4)
    const float* ro = (const float*)d_in[2];   // range_out       (B, 64, 48, 512)
    const int*   lx = (const int*)  d_in[3];   // laser_x         (B*NP, 2)
    const int*   ly = (const int*)  d_in[4];   // laser_y         (B*NP, 2)
    const float* lp = (const float*)d_in[5];   // laser_points    (B*NP, 5)
    float* out = (float*)d_out;

    int n_pillar = in_sizes[1] / 4;
    int n_laser  = in_sizes[5] / 5;

    void* winp = nullptr;
    cudaGetSymbolAddress(&winp, g_win);
    cudaMemsetAsync(winp, 0xFF, sizeof(int) * 2 * BATCH * GRID, 0);  // all -1

    int n_sc = n_pillar + n_laser;
    k_scatter<<<(n_sc + 255) / 256, 256>>>(vc, lp, n_pillar, n_laser);

    dim3 tb(32, 8);
    dim3 tg(RSP / 32, CF / 32, BATCH);         // (768, 2, 2)
    k_rot_transpose<<<tg, tb>>>(ro);

    dim3 gg(NTILES, BATCH);                    // (6846, 2)
    k_gather<<<gg, 256>>>(pf, lx, ly, lp, out);
}

// round 5
// speedup vs baseline: 1.7931x; 1.1724x over previous
#include <cuda_runtime.h>

#define BATCH   2
#define CF      64
#define NXD     468
#define NYD     468
#define GRID    (NXD * NYD)      // 219024
#define NP_PER  60000
#define HRD     48
#define WRD     512
#define RSP     (HRD * WRD)      // 24576
#define TCELL   32               // cells per gather tile (last tile has 16)
#define NTILES  ((GRID + TCELL - 1) / TCELL)   // 6846

// Winner-index maps: [0 .. B*G) spatial, [B*G .. 2*B*G) bev. -1 = empty.
__device__ __align__(16) int g_win[2 * BATCH * GRID];
// Channel-last transposed range_out: [B][RSP][64]
__device__ __align__(16) float g_rot[BATCH * RSP * CF];

#define SCAT_BLOCKS 625          // ceil(160000/256)
#define TRANS_BLOCKS (RSP / 32 * (CF / 32) * BATCH)   // 3072

// Fused prologue: blocks [0,625) scatter winners; blocks [625,3697) transpose
// range_out. The two jobs are independent -> overlap instead of serialize.
// Last-write-wins == highest point index (serial XLA scatter order).
// XLA's arcp rewrite makes v/0.16f == v*6.25f exactly (verified rel_err==0.0).
__global__ void __launch_bounds__(256) k_prologue(
        const int* __restrict__ vc, const float* __restrict__ lp,
        const float* __restrict__ ro, int n_pillar, int n_laser) {
    if (blockIdx.x < SCAT_BLOCKS) {
        int i = blockIdx.x * 256 + threadIdx.x;
        if (i < n_pillar) {
            int b   = vc[i * 4 + 0];
            int lin = vc[i * 4 + 1] + vc[i * 4 + 2] * NXD + vc[i * 4 + 3];
            if (b < 0 || b >= BATCH || lin < 0 || lin >= GRID) return;
            atomicMax(&g_win[b * GRID + lin], i);
        } else {
            int p = i - n_pillar;
            if (p >= n_laser) return;
            float x = lp[p * 5 + 1];
            float y = lp[p * 5 + 2];
            bool valid = (x > 0.0f) && (x < 69.12f) && (y > -39.68f) && (y < 39.68f)
                      && (x >= 0.0f) && (x < 468.0f) && (y >= 0.0f) && (y < 468.0f);
            if (!valid) return;
            int xi = (int)__fmul_rn(-y, 6.25f) + 248;   // XOFF
            int yi = (int)__fmul_rn(-x, 6.25f) + 432;   // YOFF
            xi = min(max(xi, 0), 495);
            yi = min(max(yi, 0), 431);
            if (xi >= NXD) return;                      // mode='drop'
            int b = p / NP_PER;
            atomicMax(&g_win[BATCH * GRID + b * GRID + yi * NXD + xi], p);
        }
    } else {
        // Transpose range_out (B,64,RSP) -> g_rot (B,RSP,64), 32x32 tiles.
        __shared__ float tile[32][33];
        int j  = blockIdx.x - SCAT_BLOCKS;
        int s0 = (j % (RSP / 32)) * 32;
        int c0 = ((j / (RSP / 32)) % (CF / 32)) * 32;
        int b  = j / (RSP / 32 * (CF / 32));
        int tx = threadIdx.x & 31, ty = threadIdx.x >> 5;   // (32, 8)
        #pragma unroll
        for (int k = 0; k < 4; k++) {
            int c = c0 + ty + k * 8;
            tile[ty + k * 8][tx] = ro[((size_t)(b * CF + c)) * RSP + s0 + tx];
        }
        __syncthreads();
        #pragma unroll
        for (int k = 0; k < 4; k++) {
            int s = s0 + ty + k * 8;
            g_rot[((size_t)(b * RSP + s)) * CF + c0 + tx] = tile[tx][ty + k * 8];
        }
    }
}

// Tiled gather: one block = 32 cells x 128 channels (16 KB of output).
// smem layout is [ch][cell] so phase 2 is a single LDS.128 + STG.128 per
// 4-cell vector (contiguous 512B per warp, conflict-free both phases).
// Output stores use __stcs (evict-first) so the 224 MB stream doesn't evict
// the L2-resident pf/g_rot/g_win read working set (~26 MB).
__global__ void __launch_bounds__(256) k_gather(
        const float* __restrict__ pf,
        const int*   __restrict__ lx,
        const int*   __restrict__ ly,
        const float* __restrict__ lp,
        float*       __restrict__ out) {
    __shared__ float s_val[128][TCELL];    // [ch][cell]
    __shared__ float s_zc[TCELL];
    __shared__ int   s_off[TCELL];
    __shared__ int   s_wiS[TCELL];

    int tile = blockIdx.x;
    int b    = blockIdx.y;
    int t    = threadIdx.x;
    int cell0  = tile * TCELL;
    int ncells = min(TCELL, GRID - cell0);

    if (t < TCELL) {
        int wiS = -1, wiB = -1;
        if (t < ncells) {
            wiS = g_win[b * GRID + cell0 + t];
            wiB = g_win[BATCH * GRID + b * GRID + cell0 + t];
        }
        s_wiS[t] = wiS;
        float zc = 0.0f; int off = -1;
        if (wiB >= 0) {
            float z = lp[wiB * 5 + 3];
            zc  = fminf(fmaxf(z, -2.0f), 4.0f);
            off = b * RSP + ly[wiB * 2 + 1] * WRD + lx[wiB * 2 + 1];
        }
        s_zc[t] = zc; s_off[t] = off;
    }
    __syncthreads();

    // Phase 1: items (cell = i&31, v = i>>5 in 0..15). Scalar STS at
    // [row][cell]: lanes are consecutive cells -> stride-1, conflict-free.
    #pragma unroll
    for (int it = 0; it < 2; it++) {
        int i = t + it * 256;
        int cell = i & 31;
        int v    = i >> 5;
        int wi = s_wiS[cell];
        float4 a = make_float4(0.f, 0.f, 0.f, 0.f);
        if (wi >= 0) a = *(const float4*)&pf[(size_t)wi * CF + v * 4];
        s_val[v * 4 + 0][cell] = a.x;
        s_val[v * 4 + 1][cell] = a.y;
        s_val[v * 4 + 2][cell] = a.z;
        s_val[v * 4 + 3][cell] = a.w;

        int off = s_off[cell];
        float4 r = make_float4(0.f, 0.f, 0.f, 0.f);
        if (off >= 0) {
            float zc = s_zc[cell];
            r = *(const float4*)&g_rot[(size_t)off * CF + v * 4];
            r.x = __fmul_rn(zc, r.x); r.y = __fmul_rn(zc, r.y);
            r.z = __fmul_rn(zc, r.z); r.w = __fmul_rn(zc, r.w);
        }
        s_val[CF + v * 4 + 0][cell] = r.x;
        s_val[CF + v * 4 + 1][cell] = r.y;
        s_val[CF + v * 4 + 2][cell] = r.z;
        s_val[CF + v * 4 + 3][cell] = r.w;
    }
    __syncthreads();

    // Phase 2: 1024 (LDS.128 -> STG.128) pairs; per warp one full 128B line
    // per channel row.
    size_t base = (size_t)b * 128 * GRID + (size_t)cell0;
    #pragma unroll
    for (int it = 0; it < 4; it++) {
        int s  = t + it * 256;
        int ch = s >> 3;
        int cv = s & 7;
        if (cv * 4 < ncells) {
            float4 o = *(const float4*)&s_val[ch][cv * 4];
            __stcs((float4*)&out[base + (size_t)ch * GRID + cv * 4], o);
        }
    }
}

extern "C" void kernel_launch(void* const* d_in, const int* in_sizes, int n_in,
                              void* d_out, int out_size) {
    const float* pf = (const float*)d_in[0];   // pillar_features (B*P_PER, 64)
    const int*   vc = (const int*)  d_in[1];   // voxel_coords    (B*P_PER, 4)
    const float* ro = (const float*)d_in[2];   // range_out       (B, 64, 48, 512)
    const int*   lx = (const int*)  d_in[3];   // laser_x         (B*NP, 2)
    const int*   ly = (const int*)  d_in[4];   // laser_y         (B*NP, 2)
    const float* lp = (const float*)d_in[5];   // laser_points    (B*NP, 5)
    float* out = (float*)d_out;

    int n_pillar = in_sizes[1] / 4;
    int n_laser  = in_sizes[5] / 5;

    void* winp = nullptr;
    cudaGetSymbolAddress(&winp, g_win);
    cudaMemsetAsync(winp, 0xFF, sizeof(int) * 2 * BATCH * GRID, 0);  // all -1

    k_prologue<<<SCAT_BLOCKS + TRANS_BLOCKS, 256>>>(vc, lp, ro, n_pillar, n_laser);

    dim3 gg(NTILES, BATCH);                    // (6846, 2)
    k_gather<<<gg, 256>>>(pf, lx, ly, lp, out);
}